// round 8
// baseline (speedup 1.0000x reference)
#include <cuda_runtime.h>

#define N_NODES   50000
#define N_REL     10
#define R2        21
#define N_TRIPLES 500000
#define ETOT      (2 * N_TRIPLES + N_NODES)   // 1,050,000 augmented edges
#define BATCH     16384
#define KEYN      (N_NODES * R2)              // keys (src*21+p)
#define SCAN_CHUNK 4096
#define SCAN_NB   ((KEYN + SCAN_CHUNK - 1) / SCAN_CHUNK)   // 257
#define MAXFLAG   32768                       // <= 2*BATCH distinct nodes
#define MAXRUNS   (MAXFLAG * R2)              // 688,128
#define TM        128                         // GEMM tile rows

// Static scratch (no runtime allocation)
__device__ int   g_colsum[KEYN];
__device__ int   g_keycnt[KEYN];
__device__ int   g_keyoff[KEYN];
__device__ int   g_scanblk[512];
__device__ int   g_sorted[ETOT];
__device__ float g_h[N_NODES * 64];
__device__ float g_nodes[N_NODES * 64];
__device__ int   g_flag[N_NODES];
__device__ int   g_list[N_NODES];
__device__ int   g_cnt[1];
__device__ int   g_pcnt[R2];
__device__ int   g_poff[R2 + 1];
__device__ int   g_ppos[R2];
__device__ int   g_nodepos[N_NODES * R2];
__device__ int   g_nrun[N_NODES];
__device__ float g_hsum[(size_t)MAXRUNS * 64];    // 176 MB
__device__ float g_runout[(size_t)MAXRUNS * 64];  // 176 MB

__device__ __forceinline__ unsigned long long pack2(float x, float y) {
    unsigned long long r;
    asm("mov.b64 %0, {%1, %2};" : "=l"(r) : "f"(x), "f"(y));
    return r;
}
__device__ __forceinline__ void ffma2(unsigned long long& acc,
                                      unsigned long long a, unsigned long long b) {
    asm("fma.rn.f32x2 %0, %1, %2, %0;" : "+l"(acc) : "l"(a), "l"(b));
}

__device__ __forceinline__ void decode_edge(int idx, const int* __restrict__ triples,
                                            int& src, int& p, int& o) {
    if (idx < N_TRIPLES) {
        src = triples[3 * idx + 0];
        p   = triples[3 * idx + 1];
        o   = triples[3 * idx + 2];
    } else if (idx < N_TRIPLES + N_NODES) {
        int i = idx - N_TRIPLES;
        src = i; p = 2 * N_REL; o = i;
    } else {
        int e = idx - N_TRIPLES - N_NODES;
        src = triples[3 * e + 2];
        p   = triples[3 * e + 1] + N_REL;
        o   = triples[3 * e + 0];
    }
}

// ---------------------------------------------------------------------------
__global__ void k_init() {
    int idx = blockIdx.x * blockDim.x + threadIdx.x;
    if (idx < KEYN) { g_colsum[idx] = 0; g_keycnt[idx] = 0; }
    if (idx < N_NODES) g_flag[idx] = 0;
    if (idx == 0) g_cnt[0] = 0;
    if (idx < R2) g_pcnt[idx] = 0;
}

// ---------------------------------------------------------------------------
__global__ void k_hist(const int* __restrict__ triples) {
    int idx = blockIdx.x * blockDim.x + threadIdx.x;
    if (idx >= ETOT) return;
    int src, p, o;
    decode_edge(idx, triples, src, p, o);
    atomicAdd(&g_colsum[p * N_NODES + o], 1);
    atomicAdd(&g_keycnt[src * R2 + p], 1);
}

// ---------------------------------------------------------------------------
// 3-pass exclusive scan of g_keycnt -> g_keyoff
// ---------------------------------------------------------------------------
__global__ void k_scanA() {
    int b = blockIdx.x, tid = threadIdx.x;
    int base = b * SCAN_CHUNK + tid * 16;
    int s = 0;
    #pragma unroll
    for (int j = 0; j < 16; j++) {
        int idx = base + j;
        if (idx < KEYN) s += g_keycnt[idx];
    }
    __shared__ int sh[256];
    sh[tid] = s; __syncthreads();
    for (int off = 128; off; off >>= 1) {
        if (tid < off) sh[tid] += sh[tid + off];
        __syncthreads();
    }
    if (tid == 0) g_scanblk[b] = sh[0];
}

__global__ void k_scanB() {
    int tid = threadIdx.x;              // 512 threads, 1 block
    __shared__ int sh[512];
    int orig = (tid < SCAN_NB) ? g_scanblk[tid] : 0;
    sh[tid] = orig; __syncthreads();
    for (int off = 1; off < 512; off <<= 1) {
        int add = (tid >= off) ? sh[tid - off] : 0;
        __syncthreads();
        sh[tid] += add;
        __syncthreads();
    }
    if (tid < SCAN_NB) g_scanblk[tid] = sh[tid] - orig;   // exclusive
}

__global__ void k_scanC() {
    int b = blockIdx.x, tid = threadIdx.x;
    int base = b * SCAN_CHUNK + tid * 16;
    int v[16];
    #pragma unroll
    for (int j = 0; j < 16; j++) {
        int idx = base + j;
        v[j] = (idx < KEYN) ? g_keycnt[idx] : 0;
    }
    int tot = 0;
    #pragma unroll
    for (int j = 0; j < 16; j++) { int t = v[j]; v[j] = tot; tot += t; }
    __shared__ int sh[256];
    sh[tid] = tot; __syncthreads();
    int orig = tot;
    for (int off = 1; off < 256; off <<= 1) {
        int add = (tid >= off) ? sh[tid - off] : 0;
        __syncthreads();
        sh[tid] += add;
        __syncthreads();
    }
    int texcl = sh[tid] - orig + g_scanblk[b];
    #pragma unroll
    for (int j = 0; j < 16; j++) {
        int idx = base + j;
        if (idx < KEYN) g_keyoff[idx] = texcl + v[j];
    }
}

// ---------------------------------------------------------------------------
// Scatter: after this, g_keyoff[k] = exclusive END of key k
// ---------------------------------------------------------------------------
__global__ void k_scatter(const int* __restrict__ triples) {
    int idx = blockIdx.x * blockDim.x + threadIdx.x;
    if (idx >= ETOT) return;
    int src, p, o;
    decode_edge(idx, triples, src, p, o);
    int pos = atomicAdd(&g_keyoff[src * R2 + p], 1);
    g_sorted[pos] = (p << 16) | o;
}

// ---------------------------------------------------------------------------
// Layer 1: 16-thread group per node, register accumulation, no atomics.
// ---------------------------------------------------------------------------
__global__ void k_layer1(const float* __restrict__ w0, const float* __restrict__ b0) {
    int t = blockIdx.x * blockDim.x + threadIdx.x;
    int u = t >> 4, lane = t & 15;
    if (u >= N_NODES) return;
    int s = (u == 0) ? 0 : g_keyoff[u * R2 - 1];
    int e = g_keyoff[u * R2 + R2 - 1];

    const float4* w0f4 = reinterpret_cast<const float4*>(w0);
    float4 acc = make_float4(0.f, 0.f, 0.f, 0.f);
    for (int i = s; i < e; i++) {
        int packed = g_sorted[i];
        int p = packed >> 16, o = packed & 0xFFFF;
        int col = p * N_NODES + o;
        float val = 1.0f / (float)g_colsum[col];
        float4 w = __ldg(w0f4 + (size_t)col * 16 + lane);
        acc.x = fmaf(val, w.x, acc.x);
        acc.y = fmaf(val, w.y, acc.y);
        acc.z = fmaf(val, w.z, acc.z);
        acc.w = fmaf(val, w.w, acc.w);
    }
    float4 bb = __ldg(reinterpret_cast<const float4*>(b0) + lane);
    float4 r = make_float4(bb.x + acc.x, bb.y + acc.y, bb.z + acc.z, bb.w + acc.w);
    *reinterpret_cast<float4*>(g_h + u * 64 + lane * 4) = r;
}

// ---------------------------------------------------------------------------
__global__ void k_flag(const int* __restrict__ batch) {
    int b = blockIdx.x * blockDim.x + threadIdx.x;
    if (b < BATCH) {
        g_flag[batch[3 * b + 0]] = 1;
        g_flag[batch[3 * b + 2]] = 1;
    }
}

// ---------------------------------------------------------------------------
// Compact flagged nodes + count runs per relation p (for GEMM buckets)
// ---------------------------------------------------------------------------
__global__ void k_compact() {
    __shared__ int sh[R2];
    int tid = threadIdx.x;
    if (tid < R2) sh[tid] = 0;
    __syncthreads();
    int u = blockIdx.x * blockDim.x + tid;
    if (u < N_NODES && g_flag[u]) {
        int i = atomicAdd(&g_cnt[0], 1);
        g_list[i] = u;
        #pragma unroll
        for (int p = 0; p < R2; p++)
            if (g_keycnt[u * R2 + p] > 0) atomicAdd(&sh[p], 1);
    }
    __syncthreads();
    if (tid < R2 && sh[tid] > 0) atomicAdd(&g_pcnt[tid], sh[tid]);
}

// ---------------------------------------------------------------------------
// Scan 21 bucket counts -> g_poff / g_ppos
// ---------------------------------------------------------------------------
__global__ void k_scan21() {
    int t = threadIdx.x;                 // 32 threads
    int c = (t < R2) ? g_pcnt[t] : 0;
    int v = c;
    #pragma unroll
    for (int off = 1; off < 32; off <<= 1) {
        int n = __shfl_up_sync(0xffffffffu, v, off);
        if (t >= off) v += n;
    }
    if (t < R2) { g_poff[t + 1] = v; g_ppos[t] = v - c; }
    if (t == 0) g_poff[0] = 0;
}

// ---------------------------------------------------------------------------
// Aggregate: one warp per flagged node. For each p-run compute
// hsum = sum val*h[o]; scatter into per-p bucket; record position per node.
// ---------------------------------------------------------------------------
__global__ void k_aggregate() {
    int t = blockIdx.x * blockDim.x + threadIdx.x;
    int w = t >> 5, lane = t & 31;
    if (w >= g_cnt[0]) return;
    int u = g_list[w];
    int s = (u == 0) ? 0 : g_keyoff[u * R2 - 1];
    int e = g_keyoff[u * R2 + R2 - 1];

    float2 hacc = make_float2(0.f, 0.f);
    int curp = -1, slot = 0;
    for (int i = s; i <= e; i++) {
        int p = -2, o = 0;
        if (i < e) {
            int pk = g_sorted[i];
            p = pk >> 16; o = pk & 0xFFFF;
        }
        if (p != curp) {
            if (curp >= 0) {
                int pos = 0;
                if (lane == 0) pos = atomicAdd(&g_ppos[curp], 1);
                pos = __shfl_sync(0xffffffffu, pos, 0);
                *reinterpret_cast<float2*>(&g_hsum[(size_t)pos * 64 + 2 * lane]) = hacc;
                if (lane == 0) g_nodepos[u * R2 + slot] = pos;
                slot++;
            }
            curp = p;
            hacc = make_float2(0.f, 0.f);
        }
        if (i < e) {
            float val = 1.0f / (float)g_colsum[p * N_NODES + o];
            float2 hv = *reinterpret_cast<const float2*>(g_h + o * 64 + 2 * lane);
            hacc.x = fmaf(val, hv.x, hacc.x);
            hacc.y = fmaf(val, hv.y, hacc.y);
        }
    }
    if (lane == 0) g_nrun[u] = slot;
}

// ---------------------------------------------------------------------------
// GEMM: per (p, tile of 128 runs): runout[128,64] = hsum[128,64] @ w1[p]
// w1 in smem packed as f32x2 col-pairs; hsum transposed+duplicated in smem.
// Thread computes 8 rows x 4 cols with fma.rn.f32x2 (FFMA2).
// Dynamic smem: ws2[2048] ull (16KB) + hsd[64*(TM+1)] ull (66KB)
// ---------------------------------------------------------------------------
__global__ __launch_bounds__(256, 2) void k_gemm(const float* __restrict__ w1) {
    extern __shared__ unsigned long long dyns[];
    unsigned long long* ws2 = dyns;                 // [k][cpair] 64*32
    unsigned long long* hsd = dyns + 2048;          // [k][row] stride TM+1

    int p = blockIdx.y;
    int start = g_poff[p], end = g_poff[p + 1];
    int m0 = start + blockIdx.x * TM;
    if (m0 >= end) return;
    int mc = min(TM, end - m0);
    int t = threadIdx.x;

    const float2* w1f2 = reinterpret_cast<const float2*>(w1 + p * 4096);
    for (int j = t; j < 2048; j += 256) {
        float2 v = __ldg(w1f2 + j);
        ws2[j] = pack2(v.x, v.y);
    }
    #pragma unroll
    for (int i = 0; i < 32; i++) {
        int idx = t + i * 256;
        int row = idx >> 6, k = idx & 63;
        float v = (row < mc) ? g_hsum[(size_t)(m0 + row) * 64 + k] : 0.f;
        hsd[k * (TM + 1) + row] = pack2(v, v);
    }
    __syncthreads();

    int cg = t & 15, rg = t >> 4;
    int r0 = rg * 8;
    unsigned long long a0[8], a1[8];
    #pragma unroll
    for (int r = 0; r < 8; r++) { a0[r] = 0ull; a1[r] = 0ull; }

    #pragma unroll 4
    for (int k = 0; k < 64; k++) {
        ulonglong2 wv = *reinterpret_cast<const ulonglong2*>(&ws2[k * 32 + cg * 2]);
        const unsigned long long* hrow = &hsd[k * (TM + 1) + r0];
        #pragma unroll
        for (int r = 0; r < 8; r++) {
            unsigned long long hv = hrow[r];
            ffma2(a0[r], hv, wv.x);
            ffma2(a1[r], hv, wv.y);
        }
    }

    #pragma unroll
    for (int r = 0; r < 8; r++) {
        int row = r0 + r;
        if (row < mc) {
            float2 lo = *reinterpret_cast<float2*>(&a0[r]);
            float2 hi = *reinterpret_cast<float2*>(&a1[r]);
            float4 o = make_float4(lo.x, lo.y, hi.x, hi.y);
            *reinterpret_cast<float4*>(g_runout + (size_t)(m0 + row) * 64 + cg * 4) = o;
        }
    }
}

// ---------------------------------------------------------------------------
// Final: nodes[u] = b1 + sum over the node's runs of runout[pos]
// ---------------------------------------------------------------------------
__global__ void k_final(const float* __restrict__ b1) {
    int t = blockIdx.x * blockDim.x + threadIdx.x;
    int w = t >> 5, lane = t & 31;
    if (w >= g_cnt[0]) return;
    int u = g_list[w];
    int nr = g_nrun[u];
    float2 acc = *reinterpret_cast<const float2*>(b1 + 2 * lane);
    const int* np = &g_nodepos[u * R2];
    for (int s2 = 0; s2 < nr; s2++) {
        int pos = np[s2];
        float2 v = *reinterpret_cast<const float2*>(&g_runout[(size_t)pos * 64 + 2 * lane]);
        acc.x += v.x; acc.y += v.y;
    }
    *reinterpret_cast<float2*>(g_nodes + u * 64 + 2 * lane) = acc;
}

// ---------------------------------------------------------------------------
__global__ void k_score(const int* __restrict__ batch, const float* __restrict__ rel,
                        float* __restrict__ out) {
    int t = blockIdx.x * blockDim.x + threadIdx.x;
    int b = t >> 5, lane = t & 31;
    if (b >= BATCH) return;
    int si = batch[3 * b + 0];
    int pi = batch[3 * b + 1];
    int oi = batch[3 * b + 2];
    const float* ns = g_nodes + si * 64;
    const float* no = g_nodes + oi * 64;
    const float* rr = rel + pi * 64;
    float a = ns[lane]      * rr[lane]      * no[lane]
            + ns[lane + 32] * rr[lane + 32] * no[lane + 32];
    #pragma unroll
    for (int off = 16; off; off >>= 1)
        a += __shfl_xor_sync(0xffffffffu, a, off);
    if (lane == 0) out[b] = a;
}

// ---------------------------------------------------------------------------
extern "C" void kernel_launch(void* const* d_in, const int* in_sizes, int n_in,
                              void* d_out, int out_size) {
    const int*   batch     = (const int*)  d_in[0];
    const int*   triples   = (const int*)  d_in[1];
    const float* w0        = (const float*)d_in[2];
    const float* b0        = (const float*)d_in[3];
    const float* w1        = (const float*)d_in[4];
    const float* b1        = (const float*)d_in[5];
    const float* relations = (const float*)d_in[6];
    float* out = (float*)d_out;

    const int TPB = 256;
    const int GEMM_SMEM = 2048 * 8 + 64 * (TM + 1) * 8;   // 82,432 B

    cudaFuncSetAttribute(k_gemm, cudaFuncAttributeMaxDynamicSharedMemorySize, GEMM_SMEM);

    k_init<<<(KEYN + TPB - 1) / TPB, TPB>>>();
    k_hist<<<(ETOT + TPB - 1) / TPB, TPB>>>(triples);
    k_scanA<<<SCAN_NB, 256>>>();
    k_scanB<<<1, 512>>>();
    k_scanC<<<SCAN_NB, 256>>>();
    k_scatter<<<(ETOT + TPB - 1) / TPB, TPB>>>(triples);
    k_layer1<<<(N_NODES * 16 + TPB - 1) / TPB, TPB>>>(w0, b0);
    k_flag<<<(BATCH + TPB - 1) / TPB, TPB>>>(batch);
    k_compact<<<(N_NODES + TPB - 1) / TPB, TPB>>>();
    k_scan21<<<1, 32>>>();
    k_aggregate<<<(MAXFLAG * 32 + TPB - 1) / TPB, TPB>>>();
    {
        dim3 g((MAXFLAG + TM - 1) / TM, R2);
        k_gemm<<<g, 256, GEMM_SMEM>>>(w1);
    }
    k_final<<<(MAXFLAG * 32 + TPB - 1) / TPB, TPB>>>(b1);
    k_score<<<(BATCH * 32 + TPB - 1) / TPB, TPB>>>(batch, relations, out);
}